// round 14
// baseline (speedup 1.0000x reference)
#include <cuda_runtime.h>
#include <cuda_fp16.h>
#include <cstdint>

#define D 256
#define MAX_NODES 100000
#define MAX_EDGES 3200000
#define SCAN_BLK 1024

// ---- device scratch (static: allocation rules) ----
static __device__ __half g_wt[D * D];                   // W transposed [n][k], fp16
static __device__ __half g_xh[(size_t)MAX_NODES * D];   // inputs @ W, fp16
static __device__ int    g_off[MAX_NODES + 1];          // CSR offsets
static __device__ int    g_cur[MAX_NODES];              // histogram / scatter cursor
static __device__ int    g_bsum[(MAX_NODES + SCAN_BLK - 1) / SCAN_BLK + 1];
static __device__ int2   g_edge[MAX_EDGES];             // packed (src, val) sorted by dst

// ---------------------------------------------------------------------------
// CSR build
// ---------------------------------------------------------------------------
__global__ __launch_bounds__(256) void hist_kernel(
    const int* __restrict__ edst, int* __restrict__ cnt, int E)
{
    int i = blockIdx.x * blockDim.x + threadIdx.x;
    int i4 = i * 4;
    if (i4 + 3 < E) {
        int4 v = *reinterpret_cast<const int4*>(edst + i4);
        atomicAdd(&cnt[v.x], 1);
        atomicAdd(&cnt[v.y], 1);
        atomicAdd(&cnt[v.z], 1);
        atomicAdd(&cnt[v.w], 1);
    } else {
        for (int e = i4; e < E; e++) atomicAdd(&cnt[edst[e]], 1);
    }
}

__global__ __launch_bounds__(SCAN_BLK) void scan1_kernel(
    const int* __restrict__ cnt, int* __restrict__ off, int* __restrict__ bsum, int n)
{
    __shared__ int s[SCAN_BLK];
    int tid = threadIdx.x;
    int i = blockIdx.x * SCAN_BLK + tid;
    int v = (i < n) ? cnt[i] : 0;
    s[tid] = v;
    __syncthreads();
#pragma unroll
    for (int d = 1; d < SCAN_BLK; d <<= 1) {
        int t = (tid >= d) ? s[tid - d] : 0;
        __syncthreads();
        s[tid] += t;
        __syncthreads();
    }
    if (i < n) off[i] = s[tid] - v;
    if (tid == SCAN_BLK - 1) bsum[blockIdx.x] = s[tid];
}

__global__ __launch_bounds__(SCAN_BLK) void scan2_kernel(int* __restrict__ bsum, int nb)
{
    __shared__ int s[SCAN_BLK];
    int tid = threadIdx.x;
    int v = (tid < nb) ? bsum[tid] : 0;
    s[tid] = v;
    __syncthreads();
#pragma unroll
    for (int d = 1; d < SCAN_BLK; d <<= 1) {
        int t = (tid >= d) ? s[tid - d] : 0;
        __syncthreads();
        s[tid] += t;
        __syncthreads();
    }
    if (tid < nb) bsum[tid] = s[tid] - v;
}

__global__ __launch_bounds__(256) void scan3_kernel(
    int* __restrict__ off, const int* __restrict__ bsum, int* __restrict__ cur,
    int n, int E)
{
    int i = blockIdx.x * blockDim.x + threadIdx.x;
    if (i < n) {
        int o = off[i] + bsum[i / SCAN_BLK];
        off[i] = o;
        cur[i] = o;
    }
    if (i == n) off[n] = E;
}

__global__ __launch_bounds__(256) void scatter_kernel(
    const int* __restrict__ esrc, const int* __restrict__ edst,
    const float* __restrict__ evals, int* __restrict__ cur,
    int2* __restrict__ edge, int E)
{
    int i = blockIdx.x * blockDim.x + threadIdx.x;
    if (i < E) {
        int d = edst[i];
        int pos = atomicAdd(&cur[d], 1);
        edge[pos] = make_int2(esrc[i], __float_as_int(evals[i]));
    }
}

// ---------------------------------------------------------------------------
// W[k][n] fp32 -> Wt[n][k] fp16, tiled transpose
// ---------------------------------------------------------------------------
__global__ __launch_bounds__(1024) void convert_w_kernel(
    const float* __restrict__ W, __half* __restrict__ Wt)
{
    __shared__ float tile[32][33];
    int bx = blockIdx.x * 32;     // n base
    int by = blockIdx.y * 32;     // k base
    int tx = threadIdx.x & 31;
    int ty = threadIdx.x >> 5;
    tile[ty][tx] = W[(by + ty) * D + bx + tx];
    __syncthreads();
    Wt[(bx + ty) * D + by + tx] = __float2half_rn(tile[tx][ty]);
}

// ---------------------------------------------------------------------------
// fp16 tensor-core GEMM with fused fp32->fp16 A conversion (R9 config, best):
//   Xh[M,256] = fp16(A32[M,256]) @ Wt^T
// CTA 128x128, 256 threads / 8 warps (4x2), warp tile 32x64, BK=32
// ---------------------------------------------------------------------------
#define BM 128
#define BN 128
#define BKH 32
#define S_H 40

__device__ __forceinline__ void cp_async16(uint32_t dst, const void* src, bool valid)
{
    int sz = valid ? 16 : 0;
    asm volatile("cp.async.ca.shared.global [%0], [%1], 16, %2;\n"
                 :: "r"(dst), "l"(src), "r"(sz));
}

__global__ __launch_bounds__(256, 2) void gemm_f16_kernel(
    const float* __restrict__ A32,  // [M][256] fp32 row-major
    const __half* __restrict__ Bt,  // [256 n][256 k] fp16 (W transposed)
    __half* __restrict__ C, int M)
{
    __shared__ __half As[2][BM * S_H];
    __shared__ __half Bs[2][BN * S_H];

    const int tid = threadIdx.x;
    const int lane = tid & 31;
    const int wid = tid >> 5;
    const int g = lane >> 2;
    const int t = lane & 3;
    const int warp_m = (wid >> 1) * 32;
    const int warp_n = (wid & 1) * 64;
    const int row0 = blockIdx.x * BM;
    const int col0 = blockIdx.y * BN;

    float c[2][8][4];
#pragma unroll
    for (int i = 0; i < 2; i++)
#pragma unroll
        for (int j = 0; j < 8; j++)
#pragma unroll
            for (int k = 0; k < 4; k++) c[i][j][k] = 0.f;

    uint32_t sB[2];
    sB[0] = (uint32_t)__cvta_generic_to_shared(&Bs[0][0]);
    sB[1] = (uint32_t)__cvta_generic_to_shared(&Bs[1][0]);

    const int r0 = (tid * 2) >> 2;
    const int c0 = ((tid * 2) & 3) * 8;
    const int r1 = (tid * 2 + 1) >> 2;
    const int c1 = ((tid * 2 + 1) & 3) * 8;
    const bool v0 = (row0 + r0) < M;
    const bool v1 = (row0 + r1) < M;

    float4 areg[2][2];

#define LDG_A(k0)                                                                     \
    do {                                                                              \
        if (v0) {                                                                     \
            const float4* p = reinterpret_cast<const float4*>(                        \
                A32 + (size_t)(row0 + r0) * 256 + (k0) + c0);                         \
            areg[0][0] = p[0]; areg[0][1] = p[1];                                     \
        } else {                                                                      \
            areg[0][0] = areg[0][1] = make_float4(0.f, 0.f, 0.f, 0.f);                \
        }                                                                             \
        if (v1) {                                                                     \
            const float4* p = reinterpret_cast<const float4*>(                        \
                A32 + (size_t)(row0 + r1) * 256 + (k0) + c1);                         \
            areg[1][0] = p[0]; areg[1][1] = p[1];                                     \
        } else {                                                                      \
            areg[1][0] = areg[1][1] = make_float4(0.f, 0.f, 0.f, 0.f);                \
        }                                                                             \
    } while (0)

#define STS_A(stage)                                                                  \
    do {                                                                              \
        __half2 h0 = __floats2half2_rn(areg[0][0].x, areg[0][0].y);                   \
        __half2 h1 = __floats2half2_rn(areg[0][0].z, areg[0][0].w);                   \
        __half2 h2 = __floats2half2_rn(areg[0][1].x, areg[0][1].y);                   \
        __half2 h3 = __floats2half2_rn(areg[0][1].z, areg[0][1].w);                   \
        *reinterpret_cast<__half2*>(&As[stage][r0 * S_H + c0 + 0]) = h0;              \
        *reinterpret_cast<__half2*>(&As[stage][r0 * S_H + c0 + 2]) = h1;              \
        *reinterpret_cast<__half2*>(&As[stage][r0 * S_H + c0 + 4]) = h2;              \
        *reinterpret_cast<__half2*>(&As[stage][r0 * S_H + c0 + 6]) = h3;              \
        h0 = __floats2half2_rn(areg[1][0].x, areg[1][0].y);                           \
        h1 = __floats2half2_rn(areg[1][0].z, areg[1][0].w);                           \
        h2 = __floats2half2_rn(areg[1][1].x, areg[1][1].y);                           \
        h3 = __floats2half2_rn(areg[1][1].z, areg[1][1].w);                           \
        *reinterpret_cast<__half2*>(&As[stage][r1 * S_H + c1 + 0]) = h0;              \
        *reinterpret_cast<__half2*>(&As[stage][r1 * S_H + c1 + 2]) = h1;              \
        *reinterpret_cast<__half2*>(&As[stage][r1 * S_H + c1 + 4]) = h2;              \
        *reinterpret_cast<__half2*>(&As[stage][r1 * S_H + c1 + 6]) = h3;              \
    } while (0)

#define LOAD_B(stage, k0)                                                             \
    do {                                                                              \
        cp_async16(sB[stage] + (uint32_t)(r0 * S_H + c0) * 2,                         \
                   Bt + (size_t)(col0 + r0) * 256 + (k0) + c0, true);                 \
        cp_async16(sB[stage] + (uint32_t)(r1 * S_H + c1) * 2,                         \
                   Bt + (size_t)(col0 + r1) * 256 + (k0) + c1, true);                 \
        asm volatile("cp.async.commit_group;\n");                                     \
    } while (0)

    LDG_A(0);
    LOAD_B(0, 0);
    STS_A(0);
    asm volatile("cp.async.wait_group 0;\n");
    __syncthreads();

    for (int k0 = 0; k0 < 256; k0 += BKH) {
        const int cur = (k0 / BKH) & 1;
        const int nxt = cur ^ 1;
        const bool more = (k0 + BKH) < 256;
        if (more) {
            LOAD_B(nxt, k0 + BKH);
            LDG_A(k0 + BKH);
        }

        const __half* as = &As[cur][0];
        const __half* bs = &Bs[cur][0];

#pragma unroll
        for (int ks = 0; ks < 2; ks++) {
            const int kl = ks * 16;
            uint32_t af[2][4];
            uint32_t bf[8][2];
#pragma unroll
            for (int mt = 0; mt < 2; mt++) {
                int mb = warp_m + mt * 16;
                af[mt][0] = *reinterpret_cast<const uint32_t*>(&as[(mb + g) * S_H + kl + 2 * t]);
                af[mt][1] = *reinterpret_cast<const uint32_t*>(&as[(mb + g + 8) * S_H + kl + 2 * t]);
                af[mt][2] = *reinterpret_cast<const uint32_t*>(&as[(mb + g) * S_H + kl + 2 * t + 8]);
                af[mt][3] = *reinterpret_cast<const uint32_t*>(&as[(mb + g + 8) * S_H + kl + 2 * t + 8]);
            }
#pragma unroll
            for (int nt = 0; nt < 8; nt++) {
                int nb = warp_n + nt * 8 + g;
                bf[nt][0] = *reinterpret_cast<const uint32_t*>(&bs[nb * S_H + kl + 2 * t]);
                bf[nt][1] = *reinterpret_cast<const uint32_t*>(&bs[nb * S_H + kl + 2 * t + 8]);
            }
#pragma unroll
            for (int mt = 0; mt < 2; mt++)
#pragma unroll
                for (int nt = 0; nt < 8; nt++) {
                    asm volatile(
                        "mma.sync.aligned.m16n8k16.row.col.f32.f16.f16.f32 "
                        "{%0,%1,%2,%3}, {%4,%5,%6,%7}, {%8,%9}, {%0,%1,%2,%3};"
                        : "+f"(c[mt][nt][0]), "+f"(c[mt][nt][1]),
                          "+f"(c[mt][nt][2]), "+f"(c[mt][nt][3])
                        : "r"(af[mt][0]), "r"(af[mt][1]), "r"(af[mt][2]), "r"(af[mt][3]),
                          "r"(bf[nt][0]), "r"(bf[nt][1]));
                }
        }

        if (more) {
            STS_A(nxt);
            asm volatile("cp.async.wait_group 0;\n");
        }
        __syncthreads();
    }

#pragma unroll
    for (int mt = 0; mt < 2; mt++) {
        int r1g = row0 + warp_m + mt * 16 + g;
        int r2g = r1g + 8;
#pragma unroll
        for (int nt = 0; nt < 8; nt++) {
            int cc = col0 + warp_n + nt * 8 + t * 2;
            if (r1g < M)
                *reinterpret_cast<__half2*>(&C[(size_t)r1g * 256 + cc]) =
                    __floats2half2_rn(c[mt][nt][0], c[mt][nt][1]);
            if (r2g < M)
                *reinterpret_cast<__half2*>(&C[(size_t)r2g * 256 + cc]) =
                    __floats2half2_rn(c[mt][nt][2], c[mt][nt][3]);
        }
    }
#undef LDG_A
#undef STS_A
#undef LOAD_B
}

// ---------------------------------------------------------------------------
// SpMM-CSR: one warp per node. Coalesced edge prefetch (lane e holds edge
// beg+e) + shfl distribution; fp16 gather, fp32 accumulate, fused ReLU.
// ---------------------------------------------------------------------------
__device__ __forceinline__ float2 h2f2(uint32_t packed)
{
    __half2 h = *reinterpret_cast<__half2*>(&packed);
    return __half22float2(h);
}

__device__ __forceinline__ void acc_row(
    float4& a0, float4& a1, uint4 r, float v)
{
    float2 f;
    f = h2f2(r.x);
    a0.x = fmaf(v, f.x, a0.x); a0.y = fmaf(v, f.y, a0.y);
    f = h2f2(r.y);
    a0.z = fmaf(v, f.x, a0.z); a0.w = fmaf(v, f.y, a0.w);
    f = h2f2(r.z);
    a1.x = fmaf(v, f.x, a1.x); a1.y = fmaf(v, f.y, a1.y);
    f = h2f2(r.w);
    a1.z = fmaf(v, f.x, a1.z); a1.w = fmaf(v, f.y, a1.w);
}

__global__ __launch_bounds__(256) void spmm_csr_kernel(
    const int* __restrict__ off, const int2* __restrict__ edge,
    const __half* __restrict__ x, float* __restrict__ out, int N)
{
    int warp = (blockIdx.x * blockDim.x + threadIdx.x) >> 5;
    int lane = threadIdx.x & 31;
    if (warp >= N) return;

    int beg = off[warp];
    int deg = off[warp + 1] - beg;

    float4 acc0 = make_float4(0.f, 0.f, 0.f, 0.f);
    float4 acc1 = make_float4(0.f, 0.f, 0.f, 0.f);

    for (int base = 0; base < deg; base += 32) {
        int rem = deg - base;
        int n = rem < 32 ? rem : 32;
        // coalesced prefetch: lane i holds edge[beg+base+i]
        int2 my = make_int2(0, 0);
        if (lane < n) my = edge[beg + base + lane];

        int e = 0;
        for (; e + 4 <= n; e += 4) {
            int s0 = __shfl_sync(0xffffffffu, my.x, e);
            int q0 = __shfl_sync(0xffffffffu, my.y, e);
            int s1 = __shfl_sync(0xffffffffu, my.x, e + 1);
            int q1 = __shfl_sync(0xffffffffu, my.y, e + 1);
            int s2 = __shfl_sync(0xffffffffu, my.x, e + 2);
            int q2 = __shfl_sync(0xffffffffu, my.y, e + 2);
            int s3 = __shfl_sync(0xffffffffu, my.x, e + 3);
            int q3 = __shfl_sync(0xffffffffu, my.y, e + 3);
            uint4 r0 = __ldg(reinterpret_cast<const uint4*>(x + (size_t)s0 * D) + lane);
            uint4 r1 = __ldg(reinterpret_cast<const uint4*>(x + (size_t)s1 * D) + lane);
            uint4 r2 = __ldg(reinterpret_cast<const uint4*>(x + (size_t)s2 * D) + lane);
            uint4 r3 = __ldg(reinterpret_cast<const uint4*>(x + (size_t)s3 * D) + lane);
            acc_row(acc0, acc1, r0, __int_as_float(q0));
            acc_row(acc0, acc1, r1, __int_as_float(q1));
            acc_row(acc0, acc1, r2, __int_as_float(q2));
            acc_row(acc0, acc1, r3, __int_as_float(q3));
        }
        for (; e < n; e++) {
            int s0 = __shfl_sync(0xffffffffu, my.x, e);
            int q0 = __shfl_sync(0xffffffffu, my.y, e);
            uint4 r0 = __ldg(reinterpret_cast<const uint4*>(x + (size_t)s0 * D) + lane);
            acc_row(acc0, acc1, r0, __int_as_float(q0));
        }
    }

    acc0.x = fmaxf(acc0.x, 0.f); acc0.y = fmaxf(acc0.y, 0.f);
    acc0.z = fmaxf(acc0.z, 0.f); acc0.w = fmaxf(acc0.w, 0.f);
    acc1.x = fmaxf(acc1.x, 0.f); acc1.y = fmaxf(acc1.y, 0.f);
    acc1.z = fmaxf(acc1.z, 0.f); acc1.w = fmaxf(acc1.w, 0.f);

    float4* o = reinterpret_cast<float4*>(out + (size_t)warp * D) + lane * 2;
    o[0] = acc0;
    o[1] = acc1;
}

// ---------------------------------------------------------------------------
// Launcher: CSR build on side stream, convW + GEMM on main stream, join,
// then SpMM.
// ---------------------------------------------------------------------------
extern "C" void kernel_launch(void* const* d_in, const int* in_sizes, int n_in,
                              void* d_out, int out_size)
{
    const float* inputs = (const float*)d_in[0];
    const float* W      = (const float*)d_in[1];
    const int*   esrc   = (const int*)  d_in[2];
    const int*   edst   = (const int*)  d_in[3];
    const float* evals  = (const float*)d_in[4];
    float*       out    = (float*)d_out;

    const int M = in_sizes[0] / D;     // 100000
    const int E = in_sizes[2];         // 3200000

    __half *wt, *xh;
    int2* edge;
    int *off, *cur, *bsum;
    cudaGetSymbolAddress((void**)&wt,   g_wt);
    cudaGetSymbolAddress((void**)&xh,   g_xh);
    cudaGetSymbolAddress((void**)&off,  g_off);
    cudaGetSymbolAddress((void**)&cur,  g_cur);
    cudaGetSymbolAddress((void**)&bsum, g_bsum);
    cudaGetSymbolAddress((void**)&edge, g_edge);

    static cudaStream_t side = nullptr;
    static cudaEvent_t  ev_fork = nullptr, ev_join = nullptr;
    if (side == nullptr) {
        cudaStreamCreateWithFlags(&side, cudaStreamNonBlocking);
        cudaEventCreateWithFlags(&ev_fork, cudaEventDisableTiming);
        cudaEventCreateWithFlags(&ev_join, cudaEventDisableTiming);
    }

    const int nblocks_scan = (M + SCAN_BLK - 1) / SCAN_BLK;

    // ---- fork ----
    cudaEventRecord(ev_fork, 0);
    cudaStreamWaitEvent(side, ev_fork, 0);

    // ---- CSR build on side stream ----
    cudaMemsetAsync(cur, 0, M * sizeof(int), side);
    hist_kernel<<<(E / 4 + 255) / 256, 256, 0, side>>>(edst, cur, E);
    scan1_kernel<<<nblocks_scan, SCAN_BLK, 0, side>>>(cur, off, bsum, M);
    scan2_kernel<<<1, SCAN_BLK, 0, side>>>(bsum, nblocks_scan);
    scan3_kernel<<<(M + 256) / 256, 256, 0, side>>>(off, bsum, cur, M, E);
    scatter_kernel<<<(E + 255) / 256, 256, 0, side>>>(esrc, edst, evals, cur, edge, E);
    cudaEventRecord(ev_join, side);

    // ---- main stream: convW, then fused-convert fp16 GEMM ----
    {
        dim3 wgrid(D / 32, D / 32);
        convert_w_kernel<<<wgrid, 1024>>>(W, wt);
        dim3 grid((M + BM - 1) / BM, D / BN);
        gemm_f16_kernel<<<grid, 256>>>(inputs, wt, xh, M);
    }

    // ---- join, then SpMM ----
    cudaStreamWaitEvent(0, ev_join, 0);
    {
        long long threads = (long long)M * 32;
        int blocks = (int)((threads + 255) / 256);
        spmm_csr_kernel<<<blocks, 256>>>(off, edge, xh, out, M);
    }
}

// round 15
// speedup vs baseline: 1.0863x; 1.0863x over previous
#include <cuda_runtime.h>
#include <cuda_fp16.h>
#include <cstdint>

#define D 256
#define MAX_NODES 100000
#define MAX_EDGES 3200000
#define SCAN_BLK 1024

// ---- device scratch (static: allocation rules) ----
static __device__ __half g_wt[D * D];                   // W transposed [n][k], fp16
static __device__ __half g_xh[(size_t)MAX_NODES * D];   // inputs @ W, fp16
static __device__ int    g_off[MAX_NODES + 1];          // CSR offsets
static __device__ int    g_cur[MAX_NODES];              // histogram / scatter cursor
static __device__ int    g_bsum[(MAX_NODES + SCAN_BLK - 1) / SCAN_BLK + 1];
static __device__ int2   g_edge[MAX_EDGES];             // packed (src, val) sorted by dst

// ---------------------------------------------------------------------------
// CSR build
// ---------------------------------------------------------------------------
__global__ __launch_bounds__(256) void hist_kernel(
    const int* __restrict__ edst, int* __restrict__ cnt, int E)
{
    int i = blockIdx.x * blockDim.x + threadIdx.x;
    int i4 = i * 4;
    if (i4 + 3 < E) {
        int4 v = *reinterpret_cast<const int4*>(edst + i4);
        atomicAdd(&cnt[v.x], 1);
        atomicAdd(&cnt[v.y], 1);
        atomicAdd(&cnt[v.z], 1);
        atomicAdd(&cnt[v.w], 1);
    } else {
        for (int e = i4; e < E; e++) atomicAdd(&cnt[edst[e]], 1);
    }
}

__global__ __launch_bounds__(SCAN_BLK) void scan1_kernel(
    const int* __restrict__ cnt, int* __restrict__ off, int* __restrict__ bsum, int n)
{
    __shared__ int s[SCAN_BLK];
    int tid = threadIdx.x;
    int i = blockIdx.x * SCAN_BLK + tid;
    int v = (i < n) ? cnt[i] : 0;
    s[tid] = v;
    __syncthreads();
#pragma unroll
    for (int d = 1; d < SCAN_BLK; d <<= 1) {
        int t = (tid >= d) ? s[tid - d] : 0;
        __syncthreads();
        s[tid] += t;
        __syncthreads();
    }
    if (i < n) off[i] = s[tid] - v;
    if (tid == SCAN_BLK - 1) bsum[blockIdx.x] = s[tid];
}

__global__ __launch_bounds__(SCAN_BLK) void scan2_kernel(int* __restrict__ bsum, int nb)
{
    __shared__ int s[SCAN_BLK];
    int tid = threadIdx.x;
    int v = (tid < nb) ? bsum[tid] : 0;
    s[tid] = v;
    __syncthreads();
#pragma unroll
    for (int d = 1; d < SCAN_BLK; d <<= 1) {
        int t = (tid >= d) ? s[tid - d] : 0;
        __syncthreads();
        s[tid] += t;
        __syncthreads();
    }
    if (tid < nb) bsum[tid] = s[tid] - v;
}

__global__ __launch_bounds__(256) void scan3_kernel(
    int* __restrict__ off, const int* __restrict__ bsum, int* __restrict__ cur,
    int n, int E)
{
    int i = blockIdx.x * blockDim.x + threadIdx.x;
    if (i < n) {
        int o = off[i] + bsum[i / SCAN_BLK];
        off[i] = o;
        cur[i] = o;
    }
    if (i == n) off[n] = E;
}

__global__ __launch_bounds__(256) void scatter_kernel(
    const int* __restrict__ esrc, const int* __restrict__ edst,
    const float* __restrict__ evals, int* __restrict__ cur,
    int2* __restrict__ edge, int E)
{
    int i = blockIdx.x * blockDim.x + threadIdx.x;
    if (i < E) {
        int d = edst[i];
        int pos = atomicAdd(&cur[d], 1);
        edge[pos] = make_int2(esrc[i], __float_as_int(evals[i]));
    }
}

// ---------------------------------------------------------------------------
// W[k][n] fp32 -> Wt[n][k] fp16, tiled transpose
// ---------------------------------------------------------------------------
__global__ __launch_bounds__(1024) void convert_w_kernel(
    const float* __restrict__ W, __half* __restrict__ Wt)
{
    __shared__ float tile[32][33];
    int bx = blockIdx.x * 32;     // n base
    int by = blockIdx.y * 32;     // k base
    int tx = threadIdx.x & 31;
    int ty = threadIdx.x >> 5;
    tile[ty][tx] = W[(by + ty) * D + bx + tx];
    __syncthreads();
    Wt[(bx + ty) * D + by + tx] = __float2half_rn(tile[tx][ty]);
}

// ---------------------------------------------------------------------------
// fp16 tensor-core GEMM with fused fp32->fp16 A conversion (R9 config, best):
//   Xh[M,256] = fp16(A32[M,256]) @ Wt^T
// CTA 128x128, 256 threads / 8 warps (4x2), warp tile 32x64, BK=32
// ---------------------------------------------------------------------------
#define BM 128
#define BN 128
#define BKH 32
#define S_H 40

__device__ __forceinline__ void cp_async16(uint32_t dst, const void* src, bool valid)
{
    int sz = valid ? 16 : 0;
    asm volatile("cp.async.ca.shared.global [%0], [%1], 16, %2;\n"
                 :: "r"(dst), "l"(src), "r"(sz));
}

__global__ __launch_bounds__(256, 2) void gemm_f16_kernel(
    const float* __restrict__ A32,  // [M][256] fp32 row-major
    const __half* __restrict__ Bt,  // [256 n][256 k] fp16 (W transposed)
    __half* __restrict__ C, int M)
{
    __shared__ __half As[2][BM * S_H];
    __shared__ __half Bs[2][BN * S_H];

    const int tid = threadIdx.x;
    const int lane = tid & 31;
    const int wid = tid >> 5;
    const int g = lane >> 2;
    const int t = lane & 3;
    const int warp_m = (wid >> 1) * 32;
    const int warp_n = (wid & 1) * 64;
    const int row0 = blockIdx.x * BM;
    const int col0 = blockIdx.y * BN;

    float c[2][8][4];
#pragma unroll
    for (int i = 0; i < 2; i++)
#pragma unroll
        for (int j = 0; j < 8; j++)
#pragma unroll
            for (int k = 0; k < 4; k++) c[i][j][k] = 0.f;

    uint32_t sB[2];
    sB[0] = (uint32_t)__cvta_generic_to_shared(&Bs[0][0]);
    sB[1] = (uint32_t)__cvta_generic_to_shared(&Bs[1][0]);

    const int r0 = (tid * 2) >> 2;
    const int c0 = ((tid * 2) & 3) * 8;
    const int r1 = (tid * 2 + 1) >> 2;
    const int c1 = ((tid * 2 + 1) & 3) * 8;
    const bool v0 = (row0 + r0) < M;
    const bool v1 = (row0 + r1) < M;

    float4 areg[2][2];

#define LDG_A(k0)                                                                     \
    do {                                                                              \
        if (v0) {                                                                     \
            const float4* p = reinterpret_cast<const float4*>(                        \
                A32 + (size_t)(row0 + r0) * 256 + (k0) + c0);                         \
            areg[0][0] = p[0]; areg[0][1] = p[1];                                     \
        } else {                                                                      \
            areg[0][0] = areg[0][1] = make_float4(0.f, 0.f, 0.f, 0.f);                \
        }                                                                             \
        if (v1) {                                                                     \
            const float4* p = reinterpret_cast<const float4*>(                        \
                A32 + (size_t)(row0 + r1) * 256 + (k0) + c1);                         \
            areg[1][0] = p[0]; areg[1][1] = p[1];                                     \
        } else {                                                                      \
            areg[1][0] = areg[1][1] = make_float4(0.f, 0.f, 0.f, 0.f);                \
        }                                                                             \
    } while (0)

#define STS_A(stage)                                                                  \
    do {                                                                              \
        __half2 h0 = __floats2half2_rn(areg[0][0].x, areg[0][0].y);                   \
        __half2 h1 = __floats2half2_rn(areg[0][0].z, areg[0][0].w);                   \
        __half2 h2 = __floats2half2_rn(areg[0][1].x, areg[0][1].y);                   \
        __half2 h3 = __floats2half2_rn(areg[0][1].z, areg[0][1].w);                   \
        *reinterpret_cast<__half2*>(&As[stage][r0 * S_H + c0 + 0]) = h0;              \
        *reinterpret_cast<__half2*>(&As[stage][r0 * S_H + c0 + 2]) = h1;              \
        *reinterpret_cast<__half2*>(&As[stage][r0 * S_H + c0 + 4]) = h2;              \
        *reinterpret_cast<__half2*>(&As[stage][r0 * S_H + c0 + 6]) = h3;              \
        h0 = __floats2half2_rn(areg[1][0].x, areg[1][0].y);                           \
        h1 = __floats2half2_rn(areg[1][0].z, areg[1][0].w);                           \
        h2 = __floats2half2_rn(areg[1][1].x, areg[1][1].y);                           \
        h3 = __floats2half2_rn(areg[1][1].z, areg[1][1].w);                           \
        *reinterpret_cast<__half2*>(&As[stage][r1 * S_H + c1 + 0]) = h0;              \
        *reinterpret_cast<__half2*>(&As[stage][r1 * S_H + c1 + 2]) = h1;              \
        *reinterpret_cast<__half2*>(&As[stage][r1 * S_H + c1 + 4]) = h2;              \
        *reinterpret_cast<__half2*>(&As[stage][r1 * S_H + c1 + 6]) = h3;              \
    } while (0)

#define LOAD_B(stage, k0)                                                             \
    do {                                                                              \
        cp_async16(sB[stage] + (uint32_t)(r0 * S_H + c0) * 2,                         \
                   Bt + (size_t)(col0 + r0) * 256 + (k0) + c0, true);                 \
        cp_async16(sB[stage] + (uint32_t)(r1 * S_H + c1) * 2,                         \
                   Bt + (size_t)(col0 + r1) * 256 + (k0) + c1, true);                 \
        asm volatile("cp.async.commit_group;\n");                                     \
    } while (0)

    LDG_A(0);
    LOAD_B(0, 0);
    STS_A(0);
    asm volatile("cp.async.wait_group 0;\n");
    __syncthreads();

    for (int k0 = 0; k0 < 256; k0 += BKH) {
        const int cur = (k0 / BKH) & 1;
        const int nxt = cur ^ 1;
        const bool more = (k0 + BKH) < 256;
        if (more) {
            LOAD_B(nxt, k0 + BKH);
            LDG_A(k0 + BKH);
        }

        const __half* as = &As[cur][0];
        const __half* bs = &Bs[cur][0];

#pragma unroll
        for (int ks = 0; ks < 2; ks++) {
            const int kl = ks * 16;
            uint32_t af[2][4];
            uint32_t bf[8][2];
#pragma unroll
            for (int mt = 0; mt < 2; mt++) {
                int mb = warp_m + mt * 16;
                af[mt][0] = *reinterpret_cast<const uint32_t*>(&as[(mb + g) * S_H + kl + 2 * t]);
                af[mt][1] = *reinterpret_cast<const uint32_t*>(&as[(mb + g + 8) * S_H + kl + 2 * t]);
                af[mt][2] = *reinterpret_cast<const uint32_t*>(&as[(mb + g) * S_H + kl + 2 * t + 8]);
                af[mt][3] = *reinterpret_cast<const uint32_t*>(&as[(mb + g + 8) * S_H + kl + 2 * t + 8]);
            }
#pragma unroll
            for (int nt = 0; nt < 8; nt++) {
                int nb = warp_n + nt * 8 + g;
                bf[nt][0] = *reinterpret_cast<const uint32_t*>(&bs[nb * S_H + kl + 2 * t]);
                bf[nt][1] = *reinterpret_cast<const uint32_t*>(&bs[nb * S_H + kl + 2 * t + 8]);
            }
#pragma unroll
            for (int mt = 0; mt < 2; mt++)
#pragma unroll
                for (int nt = 0; nt < 8; nt++) {
                    asm volatile(
                        "mma.sync.aligned.m16n8k16.row.col.f32.f16.f16.f32 "
                        "{%0,%1,%2,%3}, {%4,%5,%6,%7}, {%8,%9}, {%0,%1,%2,%3};"
                        : "+f"(c[mt][nt][0]), "+f"(c[mt][nt][1]),
                          "+f"(c[mt][nt][2]), "+f"(c[mt][nt][3])
                        : "r"(af[mt][0]), "r"(af[mt][1]), "r"(af[mt][2]), "r"(af[mt][3]),
                          "r"(bf[nt][0]), "r"(bf[nt][1]));
                }
        }

        if (more) {
            STS_A(nxt);
            asm volatile("cp.async.wait_group 0;\n");
        }
        __syncthreads();
    }

#pragma unroll
    for (int mt = 0; mt < 2; mt++) {
        int r1g = row0 + warp_m + mt * 16 + g;
        int r2g = r1g + 8;
#pragma unroll
        for (int nt = 0; nt < 8; nt++) {
            int cc = col0 + warp_n + nt * 8 + t * 2;
            if (r1g < M)
                *reinterpret_cast<__half2*>(&C[(size_t)r1g * 256 + cc]) =
                    __floats2half2_rn(c[mt][nt][0], c[mt][nt][1]);
            if (r2g < M)
                *reinterpret_cast<__half2*>(&C[(size_t)r2g * 256 + cc]) =
                    __floats2half2_rn(c[mt][nt][2], c[mt][nt][3]);
        }
    }
#undef LDG_A
#undef STS_A
#undef LOAD_B
}

// ---------------------------------------------------------------------------
// SpMM-CSR: one warp per node; 8-edge unroll (MLP=8), edges loaded as int4
// pairs (2 edges per LDG.128); fp16 gather, fp32 accumulate, fused ReLU.
// ---------------------------------------------------------------------------
__device__ __forceinline__ float2 h2f2(uint32_t packed)
{
    __half2 h = *reinterpret_cast<__half2*>(&packed);
    return __half22float2(h);
}

__device__ __forceinline__ void acc_row(
    float4& a0, float4& a1, uint4 r, float v)
{
    float2 f;
    f = h2f2(r.x);
    a0.x = fmaf(v, f.x, a0.x); a0.y = fmaf(v, f.y, a0.y);
    f = h2f2(r.y);
    a0.z = fmaf(v, f.x, a0.z); a0.w = fmaf(v, f.y, a0.w);
    f = h2f2(r.z);
    a1.x = fmaf(v, f.x, a1.x); a1.y = fmaf(v, f.y, a1.y);
    f = h2f2(r.w);
    a1.z = fmaf(v, f.x, a1.z); a1.w = fmaf(v, f.y, a1.w);
}

__global__ __launch_bounds__(256) void spmm_csr_kernel(
    const int* __restrict__ off, const int2* __restrict__ edge,
    const __half* __restrict__ x, float* __restrict__ out, int N)
{
    int warp = (blockIdx.x * blockDim.x + threadIdx.x) >> 5;
    int lane = threadIdx.x & 31;
    if (warp >= N) return;

    int beg = off[warp];
    int end = off[warp + 1];

    float4 acc0 = make_float4(0.f, 0.f, 0.f, 0.f);
    float4 acc1 = make_float4(0.f, 0.f, 0.f, 0.f);

    int e = beg;
    // peel to even index so int4 (2-edge) loads are 16B-aligned
    if ((e & 1) && e < end) {
        int2 e0 = edge[e];
        uint4 r0 = __ldg(reinterpret_cast<const uint4*>(x + (size_t)e0.x * D) + lane);
        acc_row(acc0, acc1, r0, __int_as_float(e0.y));
        e++;
    }
    // main loop: 8 edges per iteration, 4 paired edge loads, 8 gathers in flight
    for (; e + 8 <= end; e += 8) {
        const int4* p = reinterpret_cast<const int4*>(edge + e);
        int4 p0 = p[0], p1 = p[1], p2 = p[2], p3 = p[3];
        uint4 r0 = __ldg(reinterpret_cast<const uint4*>(x + (size_t)p0.x * D) + lane);
        uint4 r1 = __ldg(reinterpret_cast<const uint4*>(x + (size_t)p0.z * D) + lane);
        uint4 r2 = __ldg(reinterpret_cast<const uint4*>(x + (size_t)p1.x * D) + lane);
        uint4 r3 = __ldg(reinterpret_cast<const uint4*>(x + (size_t)p1.z * D) + lane);
        uint4 r4 = __ldg(reinterpret_cast<const uint4*>(x + (size_t)p2.x * D) + lane);
        uint4 r5 = __ldg(reinterpret_cast<const uint4*>(x + (size_t)p2.z * D) + lane);
        uint4 r6 = __ldg(reinterpret_cast<const uint4*>(x + (size_t)p3.x * D) + lane);
        uint4 r7 = __ldg(reinterpret_cast<const uint4*>(x + (size_t)p3.z * D) + lane);
        acc_row(acc0, acc1, r0, __int_as_float(p0.y));
        acc_row(acc0, acc1, r1, __int_as_float(p0.w));
        acc_row(acc0, acc1, r2, __int_as_float(p1.y));
        acc_row(acc0, acc1, r3, __int_as_float(p1.w));
        acc_row(acc0, acc1, r4, __int_as_float(p2.y));
        acc_row(acc0, acc1, r5, __int_as_float(p2.w));
        acc_row(acc0, acc1, r6, __int_as_float(p3.y));
        acc_row(acc0, acc1, r7, __int_as_float(p3.w));
    }
    // 2-edge tail (still paired loads)
    for (; e + 2 <= end; e += 2) {
        int4 p0 = *reinterpret_cast<const int4*>(edge + e);
        uint4 r0 = __ldg(reinterpret_cast<const uint4*>(x + (size_t)p0.x * D) + lane);
        uint4 r1 = __ldg(reinterpret_cast<const uint4*>(x + (size_t)p0.z * D) + lane);
        acc_row(acc0, acc1, r0, __int_as_float(p0.y));
        acc_row(acc0, acc1, r1, __int_as_float(p0.w));
    }
    if (e < end) {
        int2 e0 = edge[e];
        uint4 r0 = __ldg(reinterpret_cast<const uint4*>(x + (size_t)e0.x * D) + lane);
        acc_row(acc0, acc1, r0, __int_as_float(e0.y));
    }

    acc0.x = fmaxf(acc0.x, 0.f); acc0.y = fmaxf(acc0.y, 0.f);
    acc0.z = fmaxf(acc0.z, 0.f); acc0.w = fmaxf(acc0.w, 0.f);
    acc1.x = fmaxf(acc1.x, 0.f); acc1.y = fmaxf(acc1.y, 0.f);
    acc1.z = fmaxf(acc1.z, 0.f); acc1.w = fmaxf(acc1.w, 0.f);

    float4* o = reinterpret_cast<float4*>(out + (size_t)warp * D) + lane * 2;
    o[0] = acc0;
    o[1] = acc1;
}

// ---------------------------------------------------------------------------
// Launcher: CSR build on side stream, convW + GEMM on main stream, join,
// then SpMM.
// ---------------------------------------------------------------------------
extern "C" void kernel_launch(void* const* d_in, const int* in_sizes, int n_in,
                              void* d_out, int out_size)
{
    const float* inputs = (const float*)d_in[0];
    const float* W      = (const float*)d_in[1];
    const int*   esrc   = (const int*)  d_in[2];
    const int*   edst   = (const int*)  d_in[3];
    const float* evals  = (const float*)d_in[4];
    float*       out    = (float*)d_out;

    const int M = in_sizes[0] / D;     // 100000
    const int E = in_sizes[2];         // 3200000

    __half *wt, *xh;
    int2* edge;
    int *off, *cur, *bsum;
    cudaGetSymbolAddress((void**)&wt,   g_wt);
    cudaGetSymbolAddress((void**)&xh,   g_xh);
    cudaGetSymbolAddress((void**)&off,  g_off);
    cudaGetSymbolAddress((void**)&cur,  g_cur);
    cudaGetSymbolAddress((void**)&bsum, g_bsum);
    cudaGetSymbolAddress((void**)&edge, g_edge);

    static cudaStream_t side = nullptr;
    static cudaEvent_t  ev_fork = nullptr, ev_join = nullptr;
    if (side == nullptr) {
        cudaStreamCreateWithFlags(&side, cudaStreamNonBlocking);
        cudaEventCreateWithFlags(&ev_fork, cudaEventDisableTiming);
        cudaEventCreateWithFlags(&ev_join, cudaEventDisableTiming);
    }

    const int nblocks_scan = (M + SCAN_BLK - 1) / SCAN_BLK;

    // ---- fork ----
    cudaEventRecord(ev_fork, 0);
    cudaStreamWaitEvent(side, ev_fork, 0);

    // ---- CSR build on side stream ----
    cudaMemsetAsync(cur, 0, M * sizeof(int), side);
    hist_kernel<<<(E / 4 + 255) / 256, 256, 0, side>>>(edst, cur, E);
    scan1_kernel<<<nblocks_scan, SCAN_BLK, 0, side>>>(cur, off, bsum, M);
    scan2_kernel<<<1, SCAN_BLK, 0, side>>>(bsum, nblocks_scan);
    scan3_kernel<<<(M + 256) / 256, 256, 0, side>>>(off, bsum, cur, M, E);
    scatter_kernel<<<(E + 255) / 256, 256, 0, side>>>(esrc, edst, evals, cur, edge, E);
    cudaEventRecord(ev_join, side);

    // ---- main stream: convW, then fused-convert fp16 GEMM ----
    {
        dim3 wgrid(D / 32, D / 32);
        convert_w_kernel<<<wgrid, 1024>>>(W, wt);
        dim3 grid((M + BM - 1) / BM, D / BN);
        gemm_f16_kernel<<<grid, 256>>>(inputs, wt, xh, M);
    }

    // ---- join, then SpMM ----
    cudaStreamWaitEvent(0, ev_join, 0);
    {
        long long threads = (long long)M * 32;
        int blocks = (int)((threads + 255) / 256);
        spmm_csr_kernel<<<blocks, 256>>>(off, edge, xh, out, M);
    }
}